// round 15
// baseline (speedup 1.0000x reference)
#include <cuda_runtime.h>
#include <cuda_fp16.h>
#include <stdint.h>

#define NN  50000
#define NE  1600000
#define D   64
#define CAP 512          // bucket capacity per node (mean deg 32, 40+ sigma headroom)

// ---------------- scratch (static device globals; no allocation) ----------------
__device__ __align__(16) __half g_h0[NN * D];           // fp16 node features (ping)
__device__ __align__(16) __half g_h1[NN * D];           // fp16 node features (pong)
__device__ __align__(16) __half g_acch[NN * D];         // fp16 aggregated means
__device__ __align__(16) unsigned short g_bucket[(size_t)NN * CAP];
__device__ int g_cnt[NN];
__device__ int g_is64;

// ---------------- PDL (programmatic dependent launch) ----------------
#define GDC_LAUNCH() asm volatile("griddepcontrol.launch_dependents;" ::: "memory")
#define GDC_WAIT()   asm volatile("griddepcontrol.wait;" ::: "memory")

// ---------------- tf32 / cp.async helpers ----------------
__device__ __forceinline__ uint32_t f2tf32(float x) {
    uint32_t r;
    asm("cvt.rna.tf32.f32 %0, %1;" : "=r"(r) : "f"(x));
    return r;
}
__device__ __forceinline__ void mma_tf32(float c[4], uint32_t a0, uint32_t a1,
                                         uint32_t a2, uint32_t a3,
                                         uint32_t b0, uint32_t b1) {
    asm volatile(
        "mma.sync.aligned.m16n8k8.row.col.f32.tf32.tf32.f32 "
        "{%0,%1,%2,%3}, {%4,%5,%6,%7}, {%8,%9}, {%0,%1,%2,%3};"
        : "+f"(c[0]), "+f"(c[1]), "+f"(c[2]), "+f"(c[3])
        : "r"(a0), "r"(a1), "r"(a2), "r"(a3), "r"(b0), "r"(b1));
}
__device__ __forceinline__ uint4 tf32x4(float4 v) {
    uint4 u;
    u.x = f2tf32(v.x); u.y = f2tf32(v.y); u.z = f2tf32(v.z); u.w = f2tf32(v.w);
    return u;
}
__device__ __forceinline__ void cp_async16(uint32_t saddr, const void* gptr) {
    asm volatile("cp.async.cg.shared.global [%0], [%1], 16;" :: "r"(saddr), "l"(gptr));
}
#define CP_COMMIT() asm volatile("cp.async.commit_group;" ::: "memory")
#define CP_WAIT1()  asm volatile("cp.async.wait_group 1;" ::: "memory")
#define CP_WAIT0()  asm volatile("cp.async.wait_group 0;" ::: "memory")

// ---------------- P0: zero counters + dtype detect ----------------
__global__ void zero_detect_kernel(const long long* __restrict__ p) {
    GDC_LAUNCH();
    int i = blockIdx.x * blockDim.x + threadIdx.x;
    if (i < NN) g_cnt[i] = 0;
    if (blockIdx.x == 0) {
        long long v = p[threadIdx.x];
        int ok = (v >= 0 && v < NN) ? 1 : 0;
        int all = __syncthreads_and(ok);
        if (threadIdx.x == 0) g_is64 = all;
    }
}

// ---------------- P1: one-pass bucket CSR build (degree + placement) ----------------
__global__ void bucket_fill_kernel(const void* __restrict__ ei) {
    GDC_LAUNCH();
    GDC_WAIT();                       // needs zeroed g_cnt + g_is64
    int idx = blockIdx.x * blockDim.x + threadIdx.x;
    int e = idx * 2;
    if (e >= NE) return;
    int s0, d0, s1, d1;
    if (g_is64) {
        const longlong2* ps = reinterpret_cast<const longlong2*>(ei);
        longlong2 sp = __ldg(&ps[idx]);
        longlong2 dp = __ldg(&ps[NE / 2 + idx]);
        s0 = (int)sp.x; s1 = (int)sp.y;
        d0 = (int)dp.x; d1 = (int)dp.y;
    } else {
        const int2* ps = reinterpret_cast<const int2*>(ei);
        int2 sp = __ldg(&ps[idx]);
        int2 dp = __ldg(&ps[NE / 2 + idx]);
        s0 = sp.x; s1 = sp.y;
        d0 = dp.x; d1 = dp.y;
    }
    int slot0 = atomicAdd(&g_cnt[d0], 1);
    int slot1 = atomicAdd(&g_cnt[d1], 1);
    if (slot0 < CAP) g_bucket[(size_t)d0 * CAP + slot0] = (unsigned short)s0;
    if (slot1 < CAP) g_bucket[(size_t)d1 * CAP + slot1] = (unsigned short)s1;
}

// ---------------- P2: input projections (tf32 MMA, cp.async double buffer) ----------------
#define SA_WORDS (128 * 68)
#define SMEM_PROJ ((2 * SA_WORDS + 64 * 36) * 4)

template <int DIN>
__device__ void proj_tile_body(uint32_t* dsm, const float* __restrict__ X,
                               const float* __restrict__ W, const float* __restrict__ b,
                               int colOff, int tileIdx) {
    uint32_t* sA0 = dsm;
    uint32_t* sA1 = dsm + SA_WORDS;
    uint32_t* sW  = dsm + 2 * SA_WORDS;     // [64][36]
    const int t    = threadIdx.x;
    const int warp = t >> 5;
    const int lane = t & 31;
    const int g    = lane >> 2;
    const int tig  = lane & 3;
    const int i0   = tileIdx * 128;
    const int mrow = warp * 16;
    const int NCH  = DIN / 64;

    float c[4][4];
#pragma unroll
    for (int n = 0; n < 4; n++)
#pragma unroll
        for (int k = 0; k < 4; k++) c[n][k] = 0.f;

    auto prefetchA = [&](uint32_t* stage, int chunk) {
#pragma unroll
        for (int f = t; f < 2048; f += 256) {
            int row = f >> 4, c4 = f & 15;
            int gi  = i0 + row;
            if (gi >= NN) gi = NN - 1;
            uint32_t saddr = (uint32_t)__cvta_generic_to_shared(&stage[row * 68 + c4 * 4]);
            cp_async16(saddr, &X[(size_t)gi * DIN + chunk * 64 + c4 * 4]);
        }
    };

    prefetchA(sA0, 0);
    CP_COMMIT();

    for (int ch = 0; ch < NCH; ch++) {
        uint32_t* cur = (ch & 1) ? sA1 : sA0;
        uint32_t* nxt = (ch & 1) ? sA0 : sA1;
        if (ch + 1 < NCH) {
            prefetchA(nxt, ch + 1);
            CP_COMMIT();
            CP_WAIT1();
        } else {
            CP_WAIT0();
        }
#pragma unroll
        for (int f = t; f < 512; f += 256) {
            int row = f >> 3, c4 = f & 7;
            float4 v = *reinterpret_cast<const float4*>(&W[(size_t)(ch * 64 + row) * 32 + c4 * 4]);
            *reinterpret_cast<uint4*>(&sW[row * 36 + c4 * 4]) = tf32x4(v);
        }
        __syncthreads();
#pragma unroll
        for (int ks = 0; ks < 8; ks++) {
            uint32_t a0 = cur[(mrow + g) * 68 + ks * 8 + tig];
            uint32_t a1 = cur[(mrow + g + 8) * 68 + ks * 8 + tig];
            uint32_t a2 = cur[(mrow + g) * 68 + ks * 8 + tig + 4];
            uint32_t a3 = cur[(mrow + g + 8) * 68 + ks * 8 + tig + 4];
#pragma unroll
            for (int nt = 0; nt < 4; nt++) {
                uint32_t b0 = sW[(ks * 8 + tig) * 36 + nt * 8 + g];
                uint32_t b1 = sW[(ks * 8 + tig + 4) * 36 + nt * 8 + g];
                mma_tf32(c[nt], a0, a1, a2, a3, b0, b1);
            }
        }
        __syncthreads();
    }

#pragma unroll
    for (int nt = 0; nt < 4; nt++) {
        int col = nt * 8 + 2 * tig;
        float bx = b[col], by = b[col + 1];
        int row0 = i0 + mrow + g;
        int row1 = row0 + 8;
        int ocol = colOff + col;
        if (row0 < NN)
            *reinterpret_cast<__half2*>(&g_h0[(size_t)row0 * D + ocol]) =
                __floats2half2_rn(c[nt][0] + bx, c[nt][1] + by);
        if (row1 < NN)
            *reinterpret_cast<__half2*>(&g_h0[(size_t)row1 * D + ocol]) =
                __floats2half2_rn(c[nt][2] + bx, c[nt][3] + by);
    }
}

__global__ void __launch_bounds__(256)
proj_both_kernel(const float* __restrict__ xc, const float* __restrict__ Wp,
                 const float* __restrict__ bp, const float* __restrict__ xs,
                 const float* __restrict__ Ws, const float* __restrict__ bs) {
    extern __shared__ uint32_t dsm[];
    GDC_LAUNCH();
    // no GDC_WAIT: reads only harness inputs, writes g_h0 (no dependency on prep)
    const int T768 = (NN + 127) / 128;
    if (blockIdx.x < T768)
        proj_tile_body<768>(dsm, xc, Wp, bp, 0, blockIdx.x);
    else
        proj_tile_body<128>(dsm, xs, Ws, bs, 32, blockIdx.x - T768);
}

// ---------------- aggregation: warp per node, 2-pair fp16 tree, occupancy-pinned ----------
// 4 streams x 8 lanes; stream q owns pairs p = q, q+4, ...; main loop eats 2 pairs
// (entries 2p,2p+1,2p+8,2p+9) with a 3-level HADD2 tree and ONE fp32 convert.
__global__ void __launch_bounds__(256, 6)
aggregate_kernel(const __half* __restrict__ hin) {
    GDC_LAUNCH();
    GDC_WAIT();                       // needs buckets + hin
    int node = (blockIdx.x * blockDim.x + threadIdx.x) >> 5;
    int lane = threadIdx.x & 31;
    if (node >= NN) return;
    const int q  = lane >> 3;
    const int l8 = lane & 7;
    int deg = __ldg(&g_cnt[node]);
    int nd  = (deg < CAP) ? deg : CAP;
    const uint32_t* bpair = reinterpret_cast<const uint32_t*>(g_bucket + (size_t)node * CAP);
    const uint4* h8 = reinterpret_cast<const uint4*>(hin);

    float acc[8];
#pragma unroll
    for (int k = 0; k < 8; k++) acc[k] = 0.f;

    int p = q;
    // 2-pair chunks: pairs p and p+4 (same stream), both full
    for (; 2 * (p + 4) + 1 < nd; p += 8) {
        uint32_t pr0 = __ldg(&bpair[p]);
        uint32_t pr1 = __ldg(&bpair[p + 4]);
        int s0 = pr0 & 0xFFFFu;
        int s1 = pr0 >> 16;
        int s2 = pr1 & 0xFFFFu;
        int s3 = pr1 >> 16;
        uint4 a  = __ldg(&h8[(size_t)s0 * 8 + l8]);
        uint4 b  = __ldg(&h8[(size_t)s1 * 8 + l8]);
        uint4 cc = __ldg(&h8[(size_t)s2 * 8 + l8]);
        uint4 d  = __ldg(&h8[(size_t)s3 * 8 + l8]);
#pragma unroll
        for (int w = 0; w < 4; w++) {
            __half2 ha = *reinterpret_cast<__half2*>(&(&a.x)[w]);
            __half2 hb = *reinterpret_cast<__half2*>(&(&b.x)[w]);
            __half2 hc = *reinterpret_cast<__half2*>(&(&cc.x)[w]);
            __half2 hd = *reinterpret_cast<__half2*>(&(&d.x)[w]);
            __half2 hs = __hadd2(__hadd2(ha, hb), __hadd2(hc, hd));
            float2 fs = __half22float2(hs);
            acc[w * 2 + 0] += fs.x;
            acc[w * 2 + 1] += fs.y;
        }
    }
    // remaining single full pairs (R12 path)
    for (; 2 * p + 1 < nd; p += 4) {
        uint32_t pr = __ldg(&bpair[p]);
        int s0 = pr & 0xFFFFu;
        int s1 = pr >> 16;
        uint4 a = __ldg(&h8[(size_t)s0 * 8 + l8]);
        uint4 b = __ldg(&h8[(size_t)s1 * 8 + l8]);
#pragma unroll
        for (int w = 0; w < 4; w++) {
            __half2 ha = *reinterpret_cast<__half2*>(&(&a.x)[w]);
            __half2 hb = *reinterpret_cast<__half2*>(&(&b.x)[w]);
            __half2 hs = __hadd2(ha, hb);
            float2 fs = __half22float2(hs);
            acc[w * 2 + 0] += fs.x;
            acc[w * 2 + 1] += fs.y;
        }
    }
    // odd tail: entry nd-1 (only when nd odd), owned by stream ((nd-1)/2) & 3
    if ((nd & 1) && q == (((nd - 1) >> 1) & 3)) {
        int s0 = __ldg(&g_bucket[(size_t)node * CAP + nd - 1]);
        uint4 a = __ldg(&h8[(size_t)s0 * 8 + l8]);
#pragma unroll
        for (int w = 0; w < 4; w++) {
            float2 fa = __half22float2(*reinterpret_cast<__half2*>(&(&a.x)[w]));
            acc[w * 2 + 0] += fa.x;
            acc[w * 2 + 1] += fa.y;
        }
    }
#pragma unroll
    for (int k = 0; k < 8; k++) {
        acc[k] += __shfl_xor_sync(0xFFFFFFFFu, acc[k], 8);
        acc[k] += __shfl_xor_sync(0xFFFFFFFFu, acc[k], 16);
    }
    if (q == 0) {
        float id = 1.0f / fmaxf((float)deg, 1.0f);
        uint4 hv;
        __half2 h0 = __floats2half2_rn(acc[0] * id, acc[1] * id);
        __half2 h1 = __floats2half2_rn(acc[2] * id, acc[3] * id);
        __half2 h2 = __floats2half2_rn(acc[4] * id, acc[5] * id);
        __half2 h3 = __floats2half2_rn(acc[6] * id, acc[7] * id);
        hv.x = *reinterpret_cast<uint32_t*>(&h0);
        hv.y = *reinterpret_cast<uint32_t*>(&h1);
        hv.z = *reinterpret_cast<uint32_t*>(&h2);
        hv.w = *reinterpret_cast<uint32_t*>(&h3);
        *reinterpret_cast<uint4*>(&g_acch[(size_t)node * D + l8 * 8]) = hv;
    }
}

// ---------------- SAGE layer (tf32 MMA): relu(acc@Wl + x@Wr + bl); optional head -----------
__global__ void __launch_bounds__(256)
layer_mma_kernel(const __half* __restrict__ hin, const float* __restrict__ Wl,
                 const float* __restrict__ bl, const float* __restrict__ Wr,
                 __half* __restrict__ hout,
                 const float* __restrict__ Wo, const float* __restrict__ bo,
                 float* __restrict__ out, int doHead) {
    __shared__ uint32_t sA[64][68];
    __shared__ uint32_t sW[64][68];
    GDC_LAUNCH();
    GDC_WAIT();                       // needs g_acch from aggregate
    const int t    = threadIdx.x;
    const int warp = t >> 5;
    const int lane = t & 31;
    const int g    = lane >> 2;
    const int tig  = lane & 3;
    const int i0   = blockIdx.x * 64;
    const int mrow = (warp >> 1) * 16;
    const int nh   = (warp & 1) * 32;

    float c[4][4];
#pragma unroll
    for (int n = 0; n < 4; n++)
#pragma unroll
        for (int k = 0; k < 4; k++) c[n][k] = 0.f;

#pragma unroll
    for (int half = 0; half < 2; half++) {
        const __half* hsrc = (half == 0) ? g_acch : hin;
        const float*  Wm   = (half == 0) ? Wl : Wr;
#pragma unroll
        for (int f = t; f < 512; f += 256) {
            int row = f >> 3, c8 = f & 7;
            int gi  = i0 + row;
            uint4 hv = make_uint4(0, 0, 0, 0);
            if (gi < NN)
                hv = *reinterpret_cast<const uint4*>(&hsrc[(size_t)gi * D + c8 * 8]);
#pragma unroll
            for (int w = 0; w < 4; w++) {
                uint32_t u = (&hv.x)[w];
                float2 fv = __half22float2(*reinterpret_cast<__half2*>(&u));
                sA[row][c8 * 8 + w * 2 + 0] = f2tf32(fv.x);
                sA[row][c8 * 8 + w * 2 + 1] = f2tf32(fv.y);
            }
        }
#pragma unroll
        for (int f = t; f < 1024; f += 256) {
            int row = f >> 4, c4 = f & 15;
            float4 v = *reinterpret_cast<const float4*>(&Wm[(size_t)row * 64 + c4 * 4]);
            *reinterpret_cast<uint4*>(&sW[row][c4 * 4]) = tf32x4(v);
        }
        __syncthreads();
#pragma unroll
        for (int ks = 0; ks < 8; ks++) {
            uint32_t a0 = sA[mrow + g][ks * 8 + tig];
            uint32_t a1 = sA[mrow + g + 8][ks * 8 + tig];
            uint32_t a2 = sA[mrow + g][ks * 8 + tig + 4];
            uint32_t a3 = sA[mrow + g + 8][ks * 8 + tig + 4];
#pragma unroll
            for (int nt = 0; nt < 4; nt++) {
                uint32_t b0 = sW[ks * 8 + tig][nh + nt * 8 + g];
                uint32_t b1 = sW[ks * 8 + tig + 4][nh + nt * 8 + g];
                mma_tf32(c[nt], a0, a1, a2, a3, b0, b1);
            }
        }
        __syncthreads();
    }

    float* sAf = reinterpret_cast<float*>(sA);
#pragma unroll
    for (int nt = 0; nt < 4; nt++) {
        int col = nh + nt * 8 + 2 * tig;
        float bx = bl[col], by = bl[col + 1];
        int lrow0 = mrow + g;
        int lrow1 = lrow0 + 8;
        int row0 = i0 + lrow0;
        int row1 = i0 + lrow1;
        float2 v0 = make_float2(fmaxf(c[nt][0] + bx, 0.f), fmaxf(c[nt][1] + by, 0.f));
        float2 v1 = make_float2(fmaxf(c[nt][2] + bx, 0.f), fmaxf(c[nt][3] + by, 0.f));
        if (doHead) {
            sAf[lrow0 * 68 + col] = v0.x; sAf[lrow0 * 68 + col + 1] = v0.y;
            sAf[lrow1 * 68 + col] = v1.x; sAf[lrow1 * 68 + col + 1] = v1.y;
        }
        if (hout) {
            if (row0 < NN)
                *reinterpret_cast<__half2*>(&hout[(size_t)row0 * D + col]) =
                    __floats2half2_rn(v0.x, v0.y);
            if (row1 < NN)
                *reinterpret_cast<__half2*>(&hout[(size_t)row1 * D + col]) =
                    __floats2half2_rn(v1.x, v1.y);
        }
    }

    if (doHead) {
        __syncthreads();
        int row  = t >> 2;
        int part = t & 3;
        float p0 = 0.f, p1 = 0.f;
#pragma unroll
        for (int k = part * 16; k < part * 16 + 16; k++) {
            float a = sAf[row * 68 + k];
            p0 += a * Wo[k * 2 + 0];
            p1 += a * Wo[k * 2 + 1];
        }
        p0 += __shfl_xor_sync(0xFFFFFFFFu, p0, 1);
        p1 += __shfl_xor_sync(0xFFFFFFFFu, p1, 1);
        p0 += __shfl_xor_sync(0xFFFFFFFFu, p0, 2);
        p1 += __shfl_xor_sync(0xFFFFFFFFu, p1, 2);
        int grow = i0 + row;
        if (part == 0 && grow < NN) {
            out[grow * 2 + 0] = p0 + bo[0];
            out[grow * 2 + 1] = p1 + bo[1];
        }
    }
}

// ---------------- PDL launch helper ----------------
template <typename... Args>
static void launch_pdl(void (*kern)(Args...), dim3 grid, dim3 block, size_t smem,
                       Args... args) {
    cudaLaunchConfig_t cfg = {};
    cfg.gridDim = grid;
    cfg.blockDim = block;
    cfg.dynamicSmemBytes = smem;
    cfg.stream = 0;
    cudaLaunchAttribute attr[1];
    attr[0].id = cudaLaunchAttributeProgrammaticStreamSerialization;
    attr[0].val.programmaticStreamSerializationAllowed = 1;
    cfg.attrs = attr;
    cfg.numAttrs = 1;
    cudaLaunchKernelEx(&cfg, kern, args...);
}

// ---------------- launch ----------------
extern "C" void kernel_launch(void* const* d_in, const int* in_sizes, int n_in,
                              void* d_out, int out_size) {
    const float* x_content = (const float*)d_in[0];
    const float* x_style   = (const float*)d_in[1];
    const void*  edge_idx  = d_in[2];
    // d_in[3] = edge_type (unused)
    const float* Wp  = (const float*)d_in[4];
    const float* bp  = (const float*)d_in[5];
    const float* Ws  = (const float*)d_in[6];
    const float* bs  = (const float*)d_in[7];
    const float* Wl1 = (const float*)d_in[8];
    const float* bl1 = (const float*)d_in[9];
    const float* Wr1 = (const float*)d_in[10];
    const float* Wl2 = (const float*)d_in[11];
    const float* bl2 = (const float*)d_in[12];
    const float* Wr2 = (const float*)d_in[13];
    const float* Wl3 = (const float*)d_in[14];
    const float* bl3 = (const float*)d_in[15];
    const float* Wr3 = (const float*)d_in[16];
    const float* Wo  = (const float*)d_in[17];
    const float* bo  = (const float*)d_in[18];
    float* out = (float*)d_out;

    __half *h0, *h1;
    cudaGetSymbolAddress((void**)&h0, g_h0);
    cudaGetSymbolAddress((void**)&h1, g_h1);

    const unsigned TPB = 256;

    cudaFuncSetAttribute(proj_both_kernel,
                         cudaFuncAttributeMaxDynamicSharedMemorySize, SMEM_PROJ);

    // prep
    launch_pdl(zero_detect_kernel, dim3((NN + TPB - 1) / TPB), dim3(TPB), 0,
               (const long long*)edge_idx);
    launch_pdl(bucket_fill_kernel, dim3((NE / 2 + TPB - 1) / TPB), dim3(TPB), 0,
               (const void*)edge_idx);

    // projections -> h0
    const int T768 = (NN + 127) / 128;
    launch_pdl(proj_both_kernel, dim3(2 * T768), dim3(TPB), (size_t)SMEM_PROJ,
               x_content, Wp, bp, x_style, Ws, bs);

    const unsigned aggBlocks = (NN * 32 + TPB - 1) / TPB;
    const unsigned LB = (NN + 63) / 64;

    // layer 1: agg(h0) -> GEMM(root=h0) -> h1
    launch_pdl(aggregate_kernel, dim3(aggBlocks), dim3(TPB), 0, (const __half*)h0);
    launch_pdl(layer_mma_kernel, dim3(LB), dim3(TPB), 0,
               (const __half*)h0, Wl1, bl1, Wr1, (__half*)h1,
               (const float*)nullptr, (const float*)nullptr, (float*)nullptr, 0);

    // layer 2: agg(h1) -> GEMM(root=h1) -> h0
    launch_pdl(aggregate_kernel, dim3(aggBlocks), dim3(TPB), 0, (const __half*)h1);
    launch_pdl(layer_mma_kernel, dim3(LB), dim3(TPB), 0,
               (const __half*)h1, Wl2, bl2, Wr2, (__half*)h0,
               (const float*)nullptr, (const float*)nullptr, (float*)nullptr, 0);

    // layer 3 + head: agg(h0) -> GEMM(root=h0) -> out
    launch_pdl(aggregate_kernel, dim3(aggBlocks), dim3(TPB), 0, (const __half*)h0);
    launch_pdl(layer_mma_kernel, dim3(LB), dim3(TPB), 0,
               (const __half*)h0, Wl3, bl3, Wr3, (__half*)nullptr,
               Wo, bo, out, 1);
}

// round 16
// speedup vs baseline: 1.0100x; 1.0100x over previous
#include <cuda_runtime.h>
#include <cuda_fp16.h>
#include <stdint.h>

#define NN  50000
#define NE  1600000
#define D   64
#define CAP 512          // bucket capacity per node (mean deg 32, 40+ sigma headroom)

// ---------------- scratch (static device globals; no allocation) ----------------
__device__ __align__(16) __half g_h0[NN * D];           // fp16 node features (ping)
__device__ __align__(16) __half g_h1[NN * D];           // fp16 node features (pong)
__device__ __align__(16) __half g_acch[NN * D];         // fp16 aggregated means
__device__ __align__(16) unsigned short g_bucket[(size_t)NN * CAP];
__device__ int g_cnt[NN];
__device__ int g_is64;

// ---------------- PDL (programmatic dependent launch) ----------------
#define GDC_LAUNCH() asm volatile("griddepcontrol.launch_dependents;" ::: "memory")
#define GDC_WAIT()   asm volatile("griddepcontrol.wait;" ::: "memory")

// ---------------- tf32 / cp.async helpers ----------------
__device__ __forceinline__ uint32_t f2tf32(float x) {
    uint32_t r;
    asm("cvt.rna.tf32.f32 %0, %1;" : "=r"(r) : "f"(x));
    return r;
}
__device__ __forceinline__ void mma_tf32(float c[4], uint32_t a0, uint32_t a1,
                                         uint32_t a2, uint32_t a3,
                                         uint32_t b0, uint32_t b1) {
    asm volatile(
        "mma.sync.aligned.m16n8k8.row.col.f32.tf32.tf32.f32 "
        "{%0,%1,%2,%3}, {%4,%5,%6,%7}, {%8,%9}, {%0,%1,%2,%3};"
        : "+f"(c[0]), "+f"(c[1]), "+f"(c[2]), "+f"(c[3])
        : "r"(a0), "r"(a1), "r"(a2), "r"(a3), "r"(b0), "r"(b1));
}
__device__ __forceinline__ uint4 tf32x4(float4 v) {
    uint4 u;
    u.x = f2tf32(v.x); u.y = f2tf32(v.y); u.z = f2tf32(v.z); u.w = f2tf32(v.w);
    return u;
}
__device__ __forceinline__ void cp_async16(uint32_t saddr, const void* gptr) {
    asm volatile("cp.async.cg.shared.global [%0], [%1], 16;" :: "r"(saddr), "l"(gptr));
}
#define CP_COMMIT() asm volatile("cp.async.commit_group;" ::: "memory")
#define CP_WAIT1()  asm volatile("cp.async.wait_group 1;" ::: "memory")
#define CP_WAIT0()  asm volatile("cp.async.wait_group 0;" ::: "memory")

// ---------------- P0: zero counters + dtype detect ----------------
__global__ void zero_detect_kernel(const long long* __restrict__ p) {
    GDC_LAUNCH();
    int i = blockIdx.x * blockDim.x + threadIdx.x;
    if (i < NN) g_cnt[i] = 0;
    if (blockIdx.x == 0) {
        long long v = p[threadIdx.x];
        int ok = (v >= 0 && v < NN) ? 1 : 0;
        int all = __syncthreads_and(ok);
        if (threadIdx.x == 0) g_is64 = all;
    }
}

// ---------------- P1: one-pass bucket CSR build (degree + placement) ----------------
__global__ void bucket_fill_kernel(const void* __restrict__ ei) {
    GDC_LAUNCH();
    GDC_WAIT();                       // needs zeroed g_cnt + g_is64
    int idx = blockIdx.x * blockDim.x + threadIdx.x;
    int e = idx * 2;
    if (e >= NE) return;
    int s0, d0, s1, d1;
    if (g_is64) {
        const longlong2* ps = reinterpret_cast<const longlong2*>(ei);
        longlong2 sp = __ldg(&ps[idx]);
        longlong2 dp = __ldg(&ps[NE / 2 + idx]);
        s0 = (int)sp.x; s1 = (int)sp.y;
        d0 = (int)dp.x; d1 = (int)dp.y;
    } else {
        const int2* ps = reinterpret_cast<const int2*>(ei);
        int2 sp = __ldg(&ps[idx]);
        int2 dp = __ldg(&ps[NE / 2 + idx]);
        s0 = sp.x; s1 = sp.y;
        d0 = dp.x; d1 = dp.y;
    }
    int slot0 = atomicAdd(&g_cnt[d0], 1);
    int slot1 = atomicAdd(&g_cnt[d1], 1);
    if (slot0 < CAP) g_bucket[(size_t)d0 * CAP + slot0] = (unsigned short)s0;
    if (slot1 < CAP) g_bucket[(size_t)d1 * CAP + slot1] = (unsigned short)s1;
}

// ---------------- P2: input projections (tf32 MMA, cp.async double buffer, BM=64) ----------
// BM=64 (4 m-tiles x 2 n-halves = 8 warps), N=32, K chunks of 64, 2-stage pipeline.
#define SA_WORDS (64 * 68)
#define SMEM_PROJ ((2 * SA_WORDS + 64 * 36) * 4)   // 43 KB -> 4-5 blocks/SM

template <int DIN>
__device__ void proj_tile_body(uint32_t* dsm, const float* __restrict__ X,
                               const float* __restrict__ W, const float* __restrict__ b,
                               int colOff, int tileIdx) {
    uint32_t* sA0 = dsm;
    uint32_t* sA1 = dsm + SA_WORDS;
    uint32_t* sW  = dsm + 2 * SA_WORDS;     // [64][36]
    const int t    = threadIdx.x;
    const int warp = t >> 5;
    const int lane = t & 31;
    const int g    = lane >> 2;
    const int tig  = lane & 3;
    const int i0   = tileIdx * 64;
    const int mrow = (warp >> 1) * 16;      // 0,16,32,48
    const int nh   = (warp & 1) * 16;       // n half: cols [nh, nh+16)
    const int NCH  = DIN / 64;

    float c[2][4];
#pragma unroll
    for (int n = 0; n < 2; n++)
#pragma unroll
        for (int k = 0; k < 4; k++) c[n][k] = 0.f;

    // prefetch helper: A chunk (64 rows x 64 k = 1024 float4) -> stage buffer
    auto prefetchA = [&](uint32_t* stage, int chunk) {
#pragma unroll
        for (int f = t; f < 1024; f += 256) {
            int row = f >> 4, c4 = f & 15;
            int gi  = i0 + row;
            if (gi >= NN) gi = NN - 1;   // clamp; OOB rows discarded at store
            uint32_t saddr = (uint32_t)__cvta_generic_to_shared(&stage[row * 68 + c4 * 4]);
            cp_async16(saddr, &X[(size_t)gi * DIN + chunk * 64 + c4 * 4]);
        }
    };

    prefetchA(sA0, 0);
    CP_COMMIT();

    for (int ch = 0; ch < NCH; ch++) {
        uint32_t* cur = (ch & 1) ? sA1 : sA0;
        uint32_t* nxt = (ch & 1) ? sA0 : sA1;
        if (ch + 1 < NCH) {
            prefetchA(nxt, ch + 1);
            CP_COMMIT();
            CP_WAIT1();
        } else {
            CP_WAIT0();
        }
        // W chunk (synchronous, rna-converted)
#pragma unroll
        for (int f = t; f < 512; f += 256) {
            int row = f >> 3, c4 = f & 7;
            float4 v = *reinterpret_cast<const float4*>(&W[(size_t)(ch * 64 + row) * 32 + c4 * 4]);
            *reinterpret_cast<uint4*>(&sW[row * 36 + c4 * 4]) = tf32x4(v);
        }
        __syncthreads();
#pragma unroll
        for (int ks = 0; ks < 8; ks++) {
            uint32_t a0 = cur[(mrow + g) * 68 + ks * 8 + tig];
            uint32_t a1 = cur[(mrow + g + 8) * 68 + ks * 8 + tig];
            uint32_t a2 = cur[(mrow + g) * 68 + ks * 8 + tig + 4];
            uint32_t a3 = cur[(mrow + g + 8) * 68 + ks * 8 + tig + 4];
#pragma unroll
            for (int nt = 0; nt < 2; nt++) {
                uint32_t b0 = sW[(ks * 8 + tig) * 36 + nh + nt * 8 + g];
                uint32_t b1 = sW[(ks * 8 + tig + 4) * 36 + nh + nt * 8 + g];
                mma_tf32(c[nt], a0, a1, a2, a3, b0, b1);
            }
        }
        __syncthreads();
    }

#pragma unroll
    for (int nt = 0; nt < 2; nt++) {
        int col = nh + nt * 8 + 2 * tig;
        float bx = b[col], by = b[col + 1];
        int row0 = i0 + mrow + g;
        int row1 = row0 + 8;
        int ocol = colOff + col;
        if (row0 < NN)
            *reinterpret_cast<__half2*>(&g_h0[(size_t)row0 * D + ocol]) =
                __floats2half2_rn(c[nt][0] + bx, c[nt][1] + by);
        if (row1 < NN)
            *reinterpret_cast<__half2*>(&g_h0[(size_t)row1 * D + ocol]) =
                __floats2half2_rn(c[nt][2] + bx, c[nt][3] + by);
    }
}

__global__ void __launch_bounds__(256)
proj_both_kernel(const float* __restrict__ xc, const float* __restrict__ Wp,
                 const float* __restrict__ bp, const float* __restrict__ xs,
                 const float* __restrict__ Ws, const float* __restrict__ bs) {
    extern __shared__ uint32_t dsm[];
    GDC_LAUNCH();
    // no GDC_WAIT: reads only harness inputs, writes g_h0 (no dependency on prep)
    const int T64 = (NN + 63) / 64;          // 782 tiles per projection
    if (blockIdx.x < T64)
        proj_tile_body<768>(dsm, xc, Wp, bp, 0, blockIdx.x);
    else
        proj_tile_body<128>(dsm, xs, Ws, bs, 32, blockIdx.x - T64);
}

// ---------------- aggregation: warp per node, paired fp16 gather (R12/R14 version) --------
__global__ void aggregate_kernel(const __half* __restrict__ hin) {
    GDC_LAUNCH();
    GDC_WAIT();                       // needs buckets + hin
    int node = (blockIdx.x * blockDim.x + threadIdx.x) >> 5;
    int lane = threadIdx.x & 31;
    if (node >= NN) return;
    const int q  = lane >> 3;
    const int l8 = lane & 7;
    int deg = __ldg(&g_cnt[node]);
    int nd  = (deg < CAP) ? deg : CAP;
    const uint32_t* bpair = reinterpret_cast<const uint32_t*>(g_bucket + (size_t)node * CAP);
    const uint4* h8 = reinterpret_cast<const uint4*>(hin);

    float acc[8];
#pragma unroll
    for (int k = 0; k < 8; k++) acc[k] = 0.f;

    // full pairs: entries [2p, 2p+1], 2p+1 < nd
    for (int p = q; 2 * p + 1 < nd; p += 4) {
        uint32_t pr = __ldg(&bpair[p]);
        int s0 = pr & 0xFFFFu;
        int s1 = pr >> 16;
        uint4 a = __ldg(&h8[(size_t)s0 * 8 + l8]);
        uint4 b = __ldg(&h8[(size_t)s1 * 8 + l8]);
#pragma unroll
        for (int w = 0; w < 4; w++) {
            __half2 ha = *reinterpret_cast<__half2*>(&(&a.x)[w]);
            __half2 hb = *reinterpret_cast<__half2*>(&(&b.x)[w]);
            __half2 hs = __hadd2(ha, hb);
            float2 fs = __half22float2(hs);
            acc[w * 2 + 0] += fs.x;
            acc[w * 2 + 1] += fs.y;
        }
    }
    // odd tail: entry nd-1 (only when nd odd), owned by stream ((nd-1)/2) & 3
    if ((nd & 1) && q == (((nd - 1) >> 1) & 3)) {
        int s0 = __ldg(&g_bucket[(size_t)node * CAP + nd - 1]);
        uint4 a = __ldg(&h8[(size_t)s0 * 8 + l8]);
#pragma unroll
        for (int w = 0; w < 4; w++) {
            float2 fa = __half22float2(*reinterpret_cast<__half2*>(&(&a.x)[w]));
            acc[w * 2 + 0] += fa.x;
            acc[w * 2 + 1] += fa.y;
        }
    }
#pragma unroll
    for (int k = 0; k < 8; k++) {
        acc[k] += __shfl_xor_sync(0xFFFFFFFFu, acc[k], 8);
        acc[k] += __shfl_xor_sync(0xFFFFFFFFu, acc[k], 16);
    }
    if (q == 0) {
        float id = 1.0f / fmaxf((float)deg, 1.0f);
        uint4 hv;
        __half2 h0 = __floats2half2_rn(acc[0] * id, acc[1] * id);
        __half2 h1 = __floats2half2_rn(acc[2] * id, acc[3] * id);
        __half2 h2 = __floats2half2_rn(acc[4] * id, acc[5] * id);
        __half2 h3 = __floats2half2_rn(acc[6] * id, acc[7] * id);
        hv.x = *reinterpret_cast<uint32_t*>(&h0);
        hv.y = *reinterpret_cast<uint32_t*>(&h1);
        hv.z = *reinterpret_cast<uint32_t*>(&h2);
        hv.w = *reinterpret_cast<uint32_t*>(&h3);
        *reinterpret_cast<uint4*>(&g_acch[(size_t)node * D + l8 * 8]) = hv;
    }
}

// ---------------- SAGE layer (tf32 MMA): relu(acc@Wl + x@Wr + bl); optional head -----------
__global__ void __launch_bounds__(256)
layer_mma_kernel(const __half* __restrict__ hin, const float* __restrict__ Wl,
                 const float* __restrict__ bl, const float* __restrict__ Wr,
                 __half* __restrict__ hout,
                 const float* __restrict__ Wo, const float* __restrict__ bo,
                 float* __restrict__ out, int doHead) {
    __shared__ uint32_t sA[64][68];
    __shared__ uint32_t sW[64][68];
    GDC_LAUNCH();
    GDC_WAIT();                       // needs g_acch from aggregate
    const int t    = threadIdx.x;
    const int warp = t >> 5;
    const int lane = t & 31;
    const int g    = lane >> 2;
    const int tig  = lane & 3;
    const int i0   = blockIdx.x * 64;
    const int mrow = (warp >> 1) * 16;
    const int nh   = (warp & 1) * 32;

    float c[4][4];
#pragma unroll
    for (int n = 0; n < 4; n++)
#pragma unroll
        for (int k = 0; k < 4; k++) c[n][k] = 0.f;

#pragma unroll
    for (int half = 0; half < 2; half++) {
        const __half* hsrc = (half == 0) ? g_acch : hin;
        const float*  Wm   = (half == 0) ? Wl : Wr;
#pragma unroll
        for (int f = t; f < 512; f += 256) {
            int row = f >> 3, c8 = f & 7;
            int gi  = i0 + row;
            uint4 hv = make_uint4(0, 0, 0, 0);
            if (gi < NN)
                hv = *reinterpret_cast<const uint4*>(&hsrc[(size_t)gi * D + c8 * 8]);
#pragma unroll
            for (int w = 0; w < 4; w++) {
                uint32_t u = (&hv.x)[w];
                float2 fv = __half22float2(*reinterpret_cast<__half2*>(&u));
                sA[row][c8 * 8 + w * 2 + 0] = f2tf32(fv.x);
                sA[row][c8 * 8 + w * 2 + 1] = f2tf32(fv.y);
            }
        }
#pragma unroll
        for (int f = t; f < 1024; f += 256) {
            int row = f >> 4, c4 = f & 15;
            float4 v = *reinterpret_cast<const float4*>(&Wm[(size_t)row * 64 + c4 * 4]);
            *reinterpret_cast<uint4*>(&sW[row][c4 * 4]) = tf32x4(v);
        }
        __syncthreads();
#pragma unroll
        for (int ks = 0; ks < 8; ks++) {
            uint32_t a0 = sA[mrow + g][ks * 8 + tig];
            uint32_t a1 = sA[mrow + g + 8][ks * 8 + tig];
            uint32_t a2 = sA[mrow + g][ks * 8 + tig + 4];
            uint32_t a3 = sA[mrow + g + 8][ks * 8 + tig + 4];
#pragma unroll
            for (int nt = 0; nt < 4; nt++) {
                uint32_t b0 = sW[ks * 8 + tig][nh + nt * 8 + g];
                uint32_t b1 = sW[ks * 8 + tig + 4][nh + nt * 8 + g];
                mma_tf32(c[nt], a0, a1, a2, a3, b0, b1);
            }
        }
        __syncthreads();
    }

    float* sAf = reinterpret_cast<float*>(sA);
#pragma unroll
    for (int nt = 0; nt < 4; nt++) {
        int col = nh + nt * 8 + 2 * tig;
        float bx = bl[col], by = bl[col + 1];
        int lrow0 = mrow + g;
        int lrow1 = lrow0 + 8;
        int row0 = i0 + lrow0;
        int row1 = i0 + lrow1;
        float2 v0 = make_float2(fmaxf(c[nt][0] + bx, 0.f), fmaxf(c[nt][1] + by, 0.f));
        float2 v1 = make_float2(fmaxf(c[nt][2] + bx, 0.f), fmaxf(c[nt][3] + by, 0.f));
        if (doHead) {
            sAf[lrow0 * 68 + col] = v0.x; sAf[lrow0 * 68 + col + 1] = v0.y;
            sAf[lrow1 * 68 + col] = v1.x; sAf[lrow1 * 68 + col + 1] = v1.y;
        }
        if (hout) {
            if (row0 < NN)
                *reinterpret_cast<__half2*>(&hout[(size_t)row0 * D + col]) =
                    __floats2half2_rn(v0.x, v0.y);
            if (row1 < NN)
                *reinterpret_cast<__half2*>(&hout[(size_t)row1 * D + col]) =
                    __floats2half2_rn(v1.x, v1.y);
        }
    }

    if (doHead) {
        __syncthreads();
        int row  = t >> 2;
        int part = t & 3;
        float p0 = 0.f, p1 = 0.f;
#pragma unroll
        for (int k = part * 16; k < part * 16 + 16; k++) {
            float a = sAf[row * 68 + k];
            p0 += a * Wo[k * 2 + 0];
            p1 += a * Wo[k * 2 + 1];
        }
        p0 += __shfl_xor_sync(0xFFFFFFFFu, p0, 1);
        p1 += __shfl_xor_sync(0xFFFFFFFFu, p1, 1);
        p0 += __shfl_xor_sync(0xFFFFFFFFu, p0, 2);
        p1 += __shfl_xor_sync(0xFFFFFFFFu, p1, 2);
        int grow = i0 + row;
        if (part == 0 && grow < NN) {
            out[grow * 2 + 0] = p0 + bo[0];
            out[grow * 2 + 1] = p1 + bo[1];
        }
    }
}

// ---------------- PDL launch helper ----------------
template <typename... Args>
static void launch_pdl(void (*kern)(Args...), dim3 grid, dim3 block, size_t smem,
                       Args... args) {
    cudaLaunchConfig_t cfg = {};
    cfg.gridDim = grid;
    cfg.blockDim = block;
    cfg.dynamicSmemBytes = smem;
    cfg.stream = 0;
    cudaLaunchAttribute attr[1];
    attr[0].id = cudaLaunchAttributeProgrammaticStreamSerialization;
    attr[0].val.programmaticStreamSerializationAllowed = 1;
    cfg.attrs = attr;
    cfg.numAttrs = 1;
    cudaLaunchKernelEx(&cfg, kern, args...);
}

// ---------------- launch ----------------
extern "C" void kernel_launch(void* const* d_in, const int* in_sizes, int n_in,
                              void* d_out, int out_size) {
    const float* x_content = (const float*)d_in[0];
    const float* x_style   = (const float*)d_in[1];
    const void*  edge_idx  = d_in[2];
    // d_in[3] = edge_type (unused)
    const float* Wp  = (const float*)d_in[4];
    const float* bp  = (const float*)d_in[5];
    const float* Ws  = (const float*)d_in[6];
    const float* bs  = (const float*)d_in[7];
    const float* Wl1 = (const float*)d_in[8];
    const float* bl1 = (const float*)d_in[9];
    const float* Wr1 = (const float*)d_in[10];
    const float* Wl2 = (const float*)d_in[11];
    const float* bl2 = (const float*)d_in[12];
    const float* Wr2 = (const float*)d_in[13];
    const float* Wl3 = (const float*)d_in[14];
    const float* bl3 = (const float*)d_in[15];
    const float* Wr3 = (const float*)d_in[16];
    const float* Wo  = (const float*)d_in[17];
    const float* bo  = (const float*)d_in[18];
    float* out = (float*)d_out;

    __half *h0, *h1;
    cudaGetSymbolAddress((void**)&h0, g_h0);
    cudaGetSymbolAddress((void**)&h1, g_h1);

    const unsigned TPB = 256;

    cudaFuncSetAttribute(proj_both_kernel,
                         cudaFuncAttributeMaxDynamicSharedMemorySize, SMEM_PROJ);

    // prep
    launch_pdl(zero_detect_kernel, dim3((NN + TPB - 1) / TPB), dim3(TPB), 0,
               (const long long*)edge_idx);
    launch_pdl(bucket_fill_kernel, dim3((NE / 2 + TPB - 1) / TPB), dim3(TPB), 0,
               (const void*)edge_idx);

    // projections -> h0 (BM=64 tiles, both projections)
    const int T64 = (NN + 63) / 64;
    launch_pdl(proj_both_kernel, dim3(2 * T64), dim3(TPB), (size_t)SMEM_PROJ,
               x_content, Wp, bp, x_style, Ws, bs);

    const unsigned aggBlocks = (NN * 32 + TPB - 1) / TPB;
    const unsigned LB = (NN + 63) / 64;

    // layer 1: agg(h0) -> GEMM(root=h0) -> h1
    launch_pdl(aggregate_kernel, dim3(aggBlocks), dim3(TPB), 0, (const __half*)h0);
    launch_pdl(layer_mma_kernel, dim3(LB), dim3(TPB), 0,
               (const __half*)h0, Wl1, bl1, Wr1, (__half*)h1,
               (const float*)nullptr, (const float*)nullptr, (float*)nullptr, 0);

    // layer 2: agg(h1) -> GEMM(root=h1) -> h0
    launch_pdl(aggregate_kernel, dim3(aggBlocks), dim3(TPB), 0, (const __half*)h1);
    launch_pdl(layer_mma_kernel, dim3(LB), dim3(TPB), 0,
               (const __half*)h1, Wl2, bl2, Wr2, (__half*)h0,
               (const float*)nullptr, (const float*)nullptr, (float*)nullptr, 0);

    // layer 3 + head: agg(h0) -> GEMM(root=h0) -> out
    launch_pdl(aggregate_kernel, dim3(aggBlocks), dim3(TPB), 0, (const __half*)h0);
    launch_pdl(layer_mma_kernel, dim3(LB), dim3(TPB), 0,
               (const __half*)h0, Wl3, bl3, Wr3, (__half*)nullptr,
               Wo, bo, out, 1);
}

// round 17
// speedup vs baseline: 1.0564x; 1.0460x over previous
#include <cuda_runtime.h>
#include <cuda_fp16.h>
#include <stdint.h>

#define NN  50000
#define NE  1600000
#define D   64
#define CAP 512          // bucket capacity per node (mean deg 32, 40+ sigma headroom)

// ---------------- scratch (static device globals; no allocation) ----------------
__device__ __align__(16) __half g_h0[NN * D];           // fp16 node features (ping)
__device__ __align__(16) __half g_h1[NN * D];           // fp16 node features (pong)
__device__ __align__(16) __half g_acch[NN * D];         // fp16 aggregated means
__device__ __align__(16) unsigned short g_bucket[(size_t)NN * CAP];
__device__ int g_cnt[NN];
__device__ int g_is64;

// ---------------- PDL (programmatic dependent launch) ----------------
#define GDC_LAUNCH() asm volatile("griddepcontrol.launch_dependents;" ::: "memory")
#define GDC_WAIT()   asm volatile("griddepcontrol.wait;" ::: "memory")

// ---------------- tf32 / cp.async helpers ----------------
__device__ __forceinline__ uint32_t f2tf32(float x) {
    uint32_t r;
    asm("cvt.rna.tf32.f32 %0, %1;" : "=r"(r) : "f"(x));
    return r;
}
__device__ __forceinline__ void mma_tf32(float c[4], uint32_t a0, uint32_t a1,
                                         uint32_t a2, uint32_t a3,
                                         uint32_t b0, uint32_t b1) {
    asm volatile(
        "mma.sync.aligned.m16n8k8.row.col.f32.tf32.tf32.f32 "
        "{%0,%1,%2,%3}, {%4,%5,%6,%7}, {%8,%9}, {%0,%1,%2,%3};"
        : "+f"(c[0]), "+f"(c[1]), "+f"(c[2]), "+f"(c[3])
        : "r"(a0), "r"(a1), "r"(a2), "r"(a3), "r"(b0), "r"(b1));
}
__device__ __forceinline__ uint4 tf32x4(float4 v) {
    uint4 u;
    u.x = f2tf32(v.x); u.y = f2tf32(v.y); u.z = f2tf32(v.z); u.w = f2tf32(v.w);
    return u;
}
__device__ __forceinline__ void cp_async16(uint32_t saddr, const void* gptr) {
    asm volatile("cp.async.cg.shared.global [%0], [%1], 16;" :: "r"(saddr), "l"(gptr));
}
#define CP_COMMIT() asm volatile("cp.async.commit_group;" ::: "memory")
#define CP_WAIT1()  asm volatile("cp.async.wait_group 1;" ::: "memory")
#define CP_WAIT0()  asm volatile("cp.async.wait_group 0;" ::: "memory")

// ---------------- P0: zero counters + dtype detect ----------------
__global__ void zero_detect_kernel(const long long* __restrict__ p) {
    GDC_LAUNCH();
    int i = blockIdx.x * blockDim.x + threadIdx.x;
    if (i < NN) g_cnt[i] = 0;
    if (blockIdx.x == 0) {
        long long v = p[threadIdx.x];
        int ok = (v >= 0 && v < NN) ? 1 : 0;
        int all = __syncthreads_and(ok);
        if (threadIdx.x == 0) g_is64 = all;
    }
}

// ---------------- P1: one-pass bucket CSR build (degree + placement) ----------------
__global__ void bucket_fill_kernel(const void* __restrict__ ei) {
    GDC_LAUNCH();
    GDC_WAIT();                       // needs zeroed g_cnt + g_is64
    int idx = blockIdx.x * blockDim.x + threadIdx.x;
    int e = idx * 2;
    if (e >= NE) return;
    int s0, d0, s1, d1;
    if (g_is64) {
        const longlong2* ps = reinterpret_cast<const longlong2*>(ei);
        longlong2 sp = __ldg(&ps[idx]);
        longlong2 dp = __ldg(&ps[NE / 2 + idx]);
        s0 = (int)sp.x; s1 = (int)sp.y;
        d0 = (int)dp.x; d1 = (int)dp.y;
    } else {
        const int2* ps = reinterpret_cast<const int2*>(ei);
        int2 sp = __ldg(&ps[idx]);
        int2 dp = __ldg(&ps[NE / 2 + idx]);
        s0 = sp.x; s1 = sp.y;
        d0 = dp.x; d1 = dp.y;
    }
    int slot0 = atomicAdd(&g_cnt[d0], 1);
    int slot1 = atomicAdd(&g_cnt[d1], 1);
    if (slot0 < CAP) g_bucket[(size_t)d0 * CAP + slot0] = (unsigned short)s0;
    if (slot1 < CAP) g_bucket[(size_t)d1 * CAP + slot1] = (unsigned short)s1;
}

// ---------------- P2: input projections (tf32 MMA, cp.async double buffer, BM=64) ----------
#define SA_WORDS (64 * 68)
#define SMEM_PROJ ((2 * SA_WORDS + 64 * 36) * 4)   // 43 KB -> 4-5 blocks/SM

template <int DIN>
__device__ void proj_tile_body(uint32_t* dsm, const float* __restrict__ X,
                               const float* __restrict__ W, const float* __restrict__ b,
                               int colOff, int tileIdx) {
    uint32_t* sA0 = dsm;
    uint32_t* sA1 = dsm + SA_WORDS;
    uint32_t* sW  = dsm + 2 * SA_WORDS;     // [64][36]
    const int t    = threadIdx.x;
    const int warp = t >> 5;
    const int lane = t & 31;
    const int g    = lane >> 2;
    const int tig  = lane & 3;
    const int i0   = tileIdx * 64;
    const int mrow = (warp >> 1) * 16;      // 0,16,32,48
    const int nh   = (warp & 1) * 16;       // n half: cols [nh, nh+16)
    const int NCH  = DIN / 64;

    float c[2][4];
#pragma unroll
    for (int n = 0; n < 2; n++)
#pragma unroll
        for (int k = 0; k < 4; k++) c[n][k] = 0.f;

    auto prefetchA = [&](uint32_t* stage, int chunk) {
#pragma unroll
        for (int f = t; f < 1024; f += 256) {
            int row = f >> 4, c4 = f & 15;
            int gi  = i0 + row;
            if (gi >= NN) gi = NN - 1;   // clamp; OOB rows discarded at store
            uint32_t saddr = (uint32_t)__cvta_generic_to_shared(&stage[row * 68 + c4 * 4]);
            cp_async16(saddr, &X[(size_t)gi * DIN + chunk * 64 + c4 * 4]);
        }
    };

    prefetchA(sA0, 0);
    CP_COMMIT();

    for (int ch = 0; ch < NCH; ch++) {
        uint32_t* cur = (ch & 1) ? sA1 : sA0;
        uint32_t* nxt = (ch & 1) ? sA0 : sA1;
        if (ch + 1 < NCH) {
            prefetchA(nxt, ch + 1);
            CP_COMMIT();
            CP_WAIT1();
        } else {
            CP_WAIT0();
        }
#pragma unroll
        for (int f = t; f < 512; f += 256) {
            int row = f >> 3, c4 = f & 7;
            float4 v = *reinterpret_cast<const float4*>(&W[(size_t)(ch * 64 + row) * 32 + c4 * 4]);
            *reinterpret_cast<uint4*>(&sW[row * 36 + c4 * 4]) = tf32x4(v);
        }
        __syncthreads();
#pragma unroll
        for (int ks = 0; ks < 8; ks++) {
            uint32_t a0 = cur[(mrow + g) * 68 + ks * 8 + tig];
            uint32_t a1 = cur[(mrow + g + 8) * 68 + ks * 8 + tig];
            uint32_t a2 = cur[(mrow + g) * 68 + ks * 8 + tig + 4];
            uint32_t a3 = cur[(mrow + g + 8) * 68 + ks * 8 + tig + 4];
#pragma unroll
            for (int nt = 0; nt < 2; nt++) {
                uint32_t b0 = sW[(ks * 8 + tig) * 36 + nh + nt * 8 + g];
                uint32_t b1 = sW[(ks * 8 + tig + 4) * 36 + nh + nt * 8 + g];
                mma_tf32(c[nt], a0, a1, a2, a3, b0, b1);
            }
        }
        __syncthreads();
    }

#pragma unroll
    for (int nt = 0; nt < 2; nt++) {
        int col = nh + nt * 8 + 2 * tig;
        float bx = b[col], by = b[col + 1];
        int row0 = i0 + mrow + g;
        int row1 = row0 + 8;
        int ocol = colOff + col;
        if (row0 < NN)
            *reinterpret_cast<__half2*>(&g_h0[(size_t)row0 * D + ocol]) =
                __floats2half2_rn(c[nt][0] + bx, c[nt][1] + by);
        if (row1 < NN)
            *reinterpret_cast<__half2*>(&g_h0[(size_t)row1 * D + ocol]) =
                __floats2half2_rn(c[nt][2] + bx, c[nt][3] + by);
    }
}

__global__ void __launch_bounds__(256)
proj_both_kernel(const float* __restrict__ xc, const float* __restrict__ Wp,
                 const float* __restrict__ bp, const float* __restrict__ xs,
                 const float* __restrict__ Ws, const float* __restrict__ bs) {
    extern __shared__ uint32_t dsm[];
    GDC_LAUNCH();
    // no GDC_WAIT: reads only harness inputs, writes g_h0 (no dependency on prep)
    const int T64 = (NN + 63) / 64;          // 782 tiles per projection
    if (blockIdx.x < T64)
        proj_tile_body<768>(dsm, xc, Wp, bp, 0, blockIdx.x);
    else
        proj_tile_body<128>(dsm, xs, Ws, bs, 32, blockIdx.x - T64);
}

// ---------------- aggregation: warp per node, paired fp16 gather (R14 version) ------------
__global__ void aggregate_kernel(const __half* __restrict__ hin) {
    GDC_LAUNCH();
    GDC_WAIT();                       // needs buckets + hin
    int node = (blockIdx.x * blockDim.x + threadIdx.x) >> 5;
    int lane = threadIdx.x & 31;
    if (node >= NN) return;
    const int q  = lane >> 3;
    const int l8 = lane & 7;
    int deg = __ldg(&g_cnt[node]);
    int nd  = (deg < CAP) ? deg : CAP;
    const uint32_t* bpair = reinterpret_cast<const uint32_t*>(g_bucket + (size_t)node * CAP);
    const uint4* h8 = reinterpret_cast<const uint4*>(hin);

    float acc[8];
#pragma unroll
    for (int k = 0; k < 8; k++) acc[k] = 0.f;

    // full pairs: entries [2p, 2p+1], 2p+1 < nd
    for (int p = q; 2 * p + 1 < nd; p += 4) {
        uint32_t pr = __ldg(&bpair[p]);
        int s0 = pr & 0xFFFFu;
        int s1 = pr >> 16;
        uint4 a = __ldg(&h8[(size_t)s0 * 8 + l8]);
        uint4 b = __ldg(&h8[(size_t)s1 * 8 + l8]);
#pragma unroll
        for (int w = 0; w < 4; w++) {
            __half2 ha = *reinterpret_cast<__half2*>(&(&a.x)[w]);
            __half2 hb = *reinterpret_cast<__half2*>(&(&b.x)[w]);
            __half2 hs = __hadd2(ha, hb);
            float2 fs = __half22float2(hs);
            acc[w * 2 + 0] += fs.x;
            acc[w * 2 + 1] += fs.y;
        }
    }
    // odd tail: entry nd-1 (only when nd odd), owned by stream ((nd-1)/2) & 3
    if ((nd & 1) && q == (((nd - 1) >> 1) & 3)) {
        int s0 = __ldg(&g_bucket[(size_t)node * CAP + nd - 1]);
        uint4 a = __ldg(&h8[(size_t)s0 * 8 + l8]);
#pragma unroll
        for (int w = 0; w < 4; w++) {
            float2 fa = __half22float2(*reinterpret_cast<__half2*>(&(&a.x)[w]));
            acc[w * 2 + 0] += fa.x;
            acc[w * 2 + 1] += fa.y;
        }
    }
#pragma unroll
    for (int k = 0; k < 8; k++) {
        acc[k] += __shfl_xor_sync(0xFFFFFFFFu, acc[k], 8);
        acc[k] += __shfl_xor_sync(0xFFFFFFFFu, acc[k], 16);
    }
    if (q == 0) {
        float id = 1.0f / fmaxf((float)deg, 1.0f);
        uint4 hv;
        __half2 h0 = __floats2half2_rn(acc[0] * id, acc[1] * id);
        __half2 h1 = __floats2half2_rn(acc[2] * id, acc[3] * id);
        __half2 h2 = __floats2half2_rn(acc[4] * id, acc[5] * id);
        __half2 h3 = __floats2half2_rn(acc[6] * id, acc[7] * id);
        hv.x = *reinterpret_cast<uint32_t*>(&h0);
        hv.y = *reinterpret_cast<uint32_t*>(&h1);
        hv.z = *reinterpret_cast<uint32_t*>(&h2);
        hv.w = *reinterpret_cast<uint32_t*>(&h3);
        *reinterpret_cast<uint4*>(&g_acch[(size_t)node * D + l8 * 8]) = hv;
    }
}

// ---------------- SAGE layer (tf32 MMA): ROOT half first (no wait) -> GDC_WAIT -> ACC half -
__global__ void __launch_bounds__(256)
layer_mma_kernel(const __half* __restrict__ hin, const float* __restrict__ Wl,
                 const float* __restrict__ bl, const float* __restrict__ Wr,
                 __half* __restrict__ hout,
                 const float* __restrict__ Wo, const float* __restrict__ bo,
                 float* __restrict__ out, int doHead) {
    __shared__ uint32_t sA[64][68];
    __shared__ uint32_t sW[64][68];
    GDC_LAUNCH();
    // NOTE: no wait yet — root half depends only on hin (previous kernel's
    // predecessor), which is already complete when this kernel was enqueued
    // behind the aggregate that itself waited on hin's producer.
    const int t    = threadIdx.x;
    const int warp = t >> 5;
    const int lane = t & 31;
    const int g    = lane >> 2;
    const int tig  = lane & 3;
    const int i0   = blockIdx.x * 64;
    const int mrow = (warp >> 1) * 16;
    const int nh   = (warp & 1) * 32;

    float c[4][4];
#pragma unroll
    for (int n = 0; n < 4; n++)
#pragma unroll
        for (int k = 0; k < 4; k++) c[n][k] = 0.f;

    // halves: 0 = ROOT (hin, Wr) — runs before the PDL wait;
    //         1 = AGG  (g_acch, Wl) — after GDC_WAIT.
#pragma unroll
    for (int half = 0; half < 2; half++) {
        if (half == 1) GDC_WAIT();    // aggregate must be complete before g_acch reads
        const __half* hsrc = (half == 0) ? hin : g_acch;
        const float*  Wm   = (half == 0) ? Wr : Wl;
#pragma unroll
        for (int f = t; f < 512; f += 256) {
            int row = f >> 3, c8 = f & 7;
            int gi  = i0 + row;
            uint4 hv = make_uint4(0, 0, 0, 0);
            if (gi < NN)
                hv = *reinterpret_cast<const uint4*>(&hsrc[(size_t)gi * D + c8 * 8]);
#pragma unroll
            for (int w = 0; w < 4; w++) {
                uint32_t u = (&hv.x)[w];
                float2 fv = __half22float2(*reinterpret_cast<__half2*>(&u));
                sA[row][c8 * 8 + w * 2 + 0] = f2tf32(fv.x);
                sA[row][c8 * 8 + w * 2 + 1] = f2tf32(fv.y);
            }
        }
#pragma unroll
        for (int f = t; f < 1024; f += 256) {
            int row = f >> 4, c4 = f & 15;
            float4 v = *reinterpret_cast<const float4*>(&Wm[(size_t)row * 64 + c4 * 4]);
            *reinterpret_cast<uint4*>(&sW[row][c4 * 4]) = tf32x4(v);
        }
        __syncthreads();
#pragma unroll
        for (int ks = 0; ks < 8; ks++) {
            uint32_t a0 = sA[mrow + g][ks * 8 + tig];
            uint32_t a1 = sA[mrow + g + 8][ks * 8 + tig];
            uint32_t a2 = sA[mrow + g][ks * 8 + tig + 4];
            uint32_t a3 = sA[mrow + g + 8][ks * 8 + tig + 4];
#pragma unroll
            for (int nt = 0; nt < 4; nt++) {
                uint32_t b0 = sW[ks * 8 + tig][nh + nt * 8 + g];
                uint32_t b1 = sW[ks * 8 + tig + 4][nh + nt * 8 + g];
                mma_tf32(c[nt], a0, a1, a2, a3, b0, b1);
            }
        }
        __syncthreads();
    }

    float* sAf = reinterpret_cast<float*>(sA);
#pragma unroll
    for (int nt = 0; nt < 4; nt++) {
        int col = nh + nt * 8 + 2 * tig;
        float bx = bl[col], by = bl[col + 1];
        int lrow0 = mrow + g;
        int lrow1 = lrow0 + 8;
        int row0 = i0 + lrow0;
        int row1 = i0 + lrow1;
        float2 v0 = make_float2(fmaxf(c[nt][0] + bx, 0.f), fmaxf(c[nt][1] + by, 0.f));
        float2 v1 = make_float2(fmaxf(c[nt][2] + bx, 0.f), fmaxf(c[nt][3] + by, 0.f));
        if (doHead) {
            sAf[lrow0 * 68 + col] = v0.x; sAf[lrow0 * 68 + col + 1] = v0.y;
            sAf[lrow1 * 68 + col] = v1.x; sAf[lrow1 * 68 + col + 1] = v1.y;
        }
        if (hout) {
            if (row0 < NN)
                *reinterpret_cast<__half2*>(&hout[(size_t)row0 * D + col]) =
                    __floats2half2_rn(v0.x, v0.y);
            if (row1 < NN)
                *reinterpret_cast<__half2*>(&hout[(size_t)row1 * D + col]) =
                    __floats2half2_rn(v1.x, v1.y);
        }
    }

    if (doHead) {
        __syncthreads();
        int row  = t >> 2;
        int part = t & 3;
        float p0 = 0.f, p1 = 0.f;
#pragma unroll
        for (int k = part * 16; k < part * 16 + 16; k++) {
            float a = sAf[row * 68 + k];
            p0 += a * Wo[k * 2 + 0];
            p1 += a * Wo[k * 2 + 1];
        }
        p0 += __shfl_xor_sync(0xFFFFFFFFu, p0, 1);
        p1 += __shfl_xor_sync(0xFFFFFFFFu, p1, 1);
        p0 += __shfl_xor_sync(0xFFFFFFFFu, p0, 2);
        p1 += __shfl_xor_sync(0xFFFFFFFFu, p1, 2);
        int grow = i0 + row;
        if (part == 0 && grow < NN) {
            out[grow * 2 + 0] = p0 + bo[0];
            out[grow * 2 + 1] = p1 + bo[1];
        }
    }
}

// ---------------- PDL launch helper ----------------
template <typename... Args>
static void launch_pdl(void (*kern)(Args...), dim3 grid, dim3 block, size_t smem,
                       Args... args) {
    cudaLaunchConfig_t cfg = {};
    cfg.gridDim = grid;
    cfg.blockDim = block;
    cfg.dynamicSmemBytes = smem;
    cfg.stream = 0;
    cudaLaunchAttribute attr[1];
    attr[0].id = cudaLaunchAttributeProgrammaticStreamSerialization;
    attr[0].val.programmaticStreamSerializationAllowed = 1;
    cfg.attrs = attr;
    cfg.numAttrs = 1;
    cudaLaunchKernelEx(&cfg, kern, args...);
}

// ---------------- launch ----------------
extern "C" void kernel_launch(void* const* d_in, const int* in_sizes, int n_in,
                              void* d_out, int out_size) {
    const float* x_content = (const float*)d_in[0];
    const float* x_style   = (const float*)d_in[1];
    const void*  edge_idx  = d_in[2];
    // d_in[3] = edge_type (unused)
    const float* Wp  = (const float*)d_in[4];
    const float* bp  = (const float*)d_in[5];
    const float* Ws  = (const float*)d_in[6];
    const float* bs  = (const float*)d_in[7];
    const float* Wl1 = (const float*)d_in[8];
    const float* bl1 = (const float*)d_in[9];
    const float* Wr1 = (const float*)d_in[10];
    const float* Wl2 = (const float*)d_in[11];
    const float* bl2 = (const float*)d_in[12];
    const float* Wr2 = (const float*)d_in[13];
    const float* Wl3 = (const float*)d_in[14];
    const float* bl3 = (const float*)d_in[15];
    const float* Wr3 = (const float*)d_in[16];
    const float* Wo  = (const float*)d_in[17];
    const float* bo  = (const float*)d_in[18];
    float* out = (float*)d_out;

    __half *h0, *h1;
    cudaGetSymbolAddress((void**)&h0, g_h0);
    cudaGetSymbolAddress((void**)&h1, g_h1);

    const unsigned TPB = 256;

    cudaFuncSetAttribute(proj_both_kernel,
                         cudaFuncAttributeMaxDynamicSharedMemorySize, SMEM_PROJ);

    // prep
    launch_pdl(zero_detect_kernel, dim3((NN + TPB - 1) / TPB), dim3(TPB), 0,
               (const long long*)edge_idx);
    launch_pdl(bucket_fill_kernel, dim3((NE / 2 + TPB - 1) / TPB), dim3(TPB), 0,
               (const void*)edge_idx);

    // projections -> h0 (BM=64 tiles, both projections)
    const int T64 = (NN + 63) / 64;
    launch_pdl(proj_both_kernel, dim3(2 * T64), dim3(TPB), (size_t)SMEM_PROJ,
               x_content, Wp, bp, x_style, Ws, bs);

    const unsigned aggBlocks = (NN * 32 + TPB - 1) / TPB;
    const unsigned LB = (NN + 63) / 64;

    // layer 1: agg(h0) -> GEMM(root=h0) -> h1
    launch_pdl(aggregate_kernel, dim3(aggBlocks), dim3(TPB), 0, (const __half*)h0);
    launch_pdl(layer_mma_kernel, dim3(LB), dim3(TPB), 0,
               (const __half*)h0, Wl1, bl1, Wr1, (__half*)h1,
               (const float*)nullptr, (const float*)nullptr, (float*)nullptr, 0);

    // layer 2: agg(h1) -> GEMM(root=h1) -> h0
    launch_pdl(aggregate_kernel, dim3(aggBlocks), dim3(TPB), 0, (const __half*)h1);
    launch_pdl(layer_mma_kernel, dim3(LB), dim3(TPB), 0,
               (const __half*)h1, Wl2, bl2, Wr2, (__half*)h0,
               (const float*)nullptr, (const float*)nullptr, (float*)nullptr, 0);

    // layer 3 + head: agg(h0) -> GEMM(root=h0) -> out
    launch_pdl(aggregate_kernel, dim3(aggBlocks), dim3(TPB), 0, (const __half*)h0);
    launch_pdl(layer_mma_kernel, dim3(LB), dim3(TPB), 0,
               (const __half*)h0, Wl3, bl3, Wr3, (__half*)nullptr,
               Wo, bo, out, 1);
}